// round 2
// baseline (speedup 1.0000x reference)
#include <cuda_runtime.h>

// Problem constants
#define B_  2
#define T_  4096
#define H_  8
#define D_  64
#define C_  64                 // chunk length
#define NC_ (T_/C_)            // 64 chunks
#define BH_ (B_*H_)            // 16
#define ROWSTRIDE (H_*D_)      // 512 floats between consecutive t

// Scratch: per-(bh,chunk) DxD matrix (pass1 sums -> pass2 exclusive prefix). 16MB, L2-resident.
__device__ float g_S[(size_t)BH_ * NC_ * D_ * D_];

// ---------------------------------------------------------------------------
// Pass 1: S[bh][c][d][e] = sum_s V[s][d] * K[s][e]
// 128-thread CTA handles 2 chunks; 64 threads per chunk, 8x8 register tiles.
// ---------------------------------------------------------------------------
#define SMEM1_BYTES (2 * 2 * C_ * D_ * (int)sizeof(float))   // 65536

__global__ void __launch_bounds__(128, 4) chunk_sum_kernel(const float* __restrict__ k,
                                                           const float* __restrict__ v) {
    extern __shared__ float sm1[];
    int tid  = threadIdx.x;
    int g    = tid >> 6;          // chunk sub-group 0/1
    int tid2 = tid & 63;

    float* Ks = sm1 + g * (2 * C_ * D_);            // [s][e] 64x64
    float* Vs = Ks + C_ * D_;                       // [s][d] 64x64

    int blk = blockIdx.x;                 // [0, 512)
    int bh  = blk >> 5;
    int c   = (blk & 31) * 2 + g;
    int b   = bh >> 3, h = bh & 7;

    const float* kbase = k + (((size_t)b * T_ + (size_t)c * C_) * H_ + h) * D_;
    const float* vbase = v + (((size_t)b * T_ + (size_t)c * C_) * H_ + h) * D_;

    // Fill (direct layout, coalesced gmem, conflict-free STS.128)
    #pragma unroll
    for (int f = tid2; f < C_ * D_ / 4; f += 64) {
        int s = f >> 4;
        int c4 = f & 15;
        ((float4*)Ks)[f] = *(const float4*)(kbase + (size_t)s * ROWSTRIDE + c4 * 4);
        ((float4*)Vs)[f] = *(const float4*)(vbase + (size_t)s * ROWSTRIDE + c4 * 4);
    }
    __syncthreads();

    int rg = tid2 >> 3, cg = tid2 & 7;
    int d0 = rg * 8, e0 = cg * 8;
    float acc[8][8] = {};
    #pragma unroll 4
    for (int s = 0; s < C_; s++) {
        float4 va0 = *(const float4*)&Vs[s * D_ + d0];
        float4 va1 = *(const float4*)&Vs[s * D_ + d0 + 4];
        float4 ka0 = *(const float4*)&Ks[s * D_ + e0];
        float4 ka1 = *(const float4*)&Ks[s * D_ + e0 + 4];
        float va[8] = {va0.x, va0.y, va0.z, va0.w, va1.x, va1.y, va1.z, va1.w};
        float ka[8] = {ka0.x, ka0.y, ka0.z, ka0.w, ka1.x, ka1.y, ka1.z, ka1.w};
        #pragma unroll
        for (int i = 0; i < 8; i++)
            #pragma unroll
            for (int j = 0; j < 8; j++)
                acc[i][j] += va[i] * ka[j];
    }

    float* Sout = g_S + ((size_t)bh * NC_ + c) * D_ * D_;
    #pragma unroll
    for (int i = 0; i < 8; i++) {
        *(float4*)&Sout[(d0 + i) * D_ + e0] =
            make_float4(acc[i][0], acc[i][1], acc[i][2], acc[i][3]);
        *(float4*)&Sout[(d0 + i) * D_ + e0 + 4] =
            make_float4(acc[i][4], acc[i][5], acc[i][6], acc[i][7]);
    }
}

// ---------------------------------------------------------------------------
// Pass 2: in-place EXCLUSIVE prefix over the chunk axis for every (bh, d, e).
// ---------------------------------------------------------------------------
__global__ void __launch_bounds__(256) prefix_kernel() {
    int gidx = blockIdx.x * 256 + threadIdx.x;   // [0, BH_*D_*D_)
    int bh  = gidx >> 12;
    int idx = gidx & 4095;
    float* base = g_S + (size_t)bh * NC_ * D_ * D_ + idx;

    float vals[NC_];
    #pragma unroll
    for (int c = 0; c < NC_; c++) vals[c] = base[(size_t)c * D_ * D_];
    float run = 0.f;
    #pragma unroll
    for (int c = 0; c < NC_; c++) { float t = vals[c]; vals[c] = run; run += t; }
    #pragma unroll
    for (int c = 0; c < NC_; c++) base[(size_t)c * D_ * D_] = vals[c];
}

// ---------------------------------------------------------------------------
// Pass 3: Y = tril(Q K^T) V + Q M_prev^T per (bh, chunk) tile.
// 128-thread CTA handles 2 chunks; 64 threads per chunk, 8x8 register tiles.
// One 68-padded buffer is reused for K^T -> A^T -> M^T to fit 2 CTAs/SM.
// ---------------------------------------------------------------------------
#define PAD_ (C_ + 4)   // 68
#define CHUNK3_FLOATS (2 * D_ * PAD_ + C_ * D_)            // Qt + (Kt/At/Mt) + Vs
#define SMEM3_BYTES (2 * CHUNK3_FLOATS * (int)sizeof(float))  // 102400

__global__ void __launch_bounds__(128, 4) output_kernel(const float* __restrict__ q,
                                                        const float* __restrict__ k,
                                                        const float* __restrict__ v,
                                                        float* __restrict__ y) {
    extern __shared__ float sm[];
    int tid  = threadIdx.x;
    int g    = tid >> 6;
    int tid2 = tid & 63;

    float* base = sm + g * CHUNK3_FLOATS;
    float (*Qt)[PAD_] = (float(*)[PAD_])(base);                 // [e][t]
    float (*Xt)[PAD_] = (float(*)[PAD_])(base + D_ * PAD_);     // Kt[e][s] -> At[s][t] -> Mt[e][d]
    float (*Vs)[D_]   = (float(*)[D_])  (base + 2 * D_ * PAD_); // [s][d]

    int blk = blockIdx.x;                 // [0, 512)
    int bh  = blk >> 5;
    int c   = (blk & 31) * 2 + g;
    int b   = bh >> 3, h = bh & 7;

    const float* qbase = q + (((size_t)b * T_ + (size_t)c * C_) * H_ + h) * D_;
    const float* kbase = k + (((size_t)b * T_ + (size_t)c * C_) * H_ + h) * D_;
    const float* vbase = v + (((size_t)b * T_ + (size_t)c * C_) * H_ + h) * D_;
    const float* Mbase = g_S + ((size_t)bh * NC_ + c) * D_ * D_;

    // Fill Qt, Kt (transposed) and Vs (direct)
    #pragma unroll
    for (int f = tid2; f < C_ * D_ / 4; f += 64) {
        int r = f >> 4;       // t row
        int cc = (f & 15) * 4;
        float4 qv = *(const float4*)(qbase + (size_t)r * ROWSTRIDE + cc);
        Qt[cc + 0][r] = qv.x; Qt[cc + 1][r] = qv.y; Qt[cc + 2][r] = qv.z; Qt[cc + 3][r] = qv.w;
        float4 kv = *(const float4*)(kbase + (size_t)r * ROWSTRIDE + cc);
        Xt[cc + 0][r] = kv.x; Xt[cc + 1][r] = kv.y; Xt[cc + 2][r] = kv.z; Xt[cc + 3][r] = kv.w;
        float4 vv = *(const float4*)(vbase + (size_t)r * ROWSTRIDE + cc);
        ((float4*)Vs)[f] = vv;
    }
    __syncthreads();

    int rg = tid2 >> 3, cg = tid2 & 7;
    int t0 = rg * 8, s0 = cg * 8;
    int d0 = s0;                      // phase-B column group

    float acc[8][8];
    #pragma unroll
    for (int i = 0; i < 8; i++)
        #pragma unroll
        for (int j = 0; j < 8; j++) acc[i][j] = 0.f;

    // Phase A: acc[i][j] = A[t0+i][s0+j] = sum_e Q[t][e] K[s][e]
    #pragma unroll 4
    for (int e = 0; e < D_; e++) {
        float4 q0 = *(const float4*)&Qt[e][t0];
        float4 q1 = *(const float4*)&Qt[e][t0 + 4];
        float4 k0 = *(const float4*)&Xt[e][s0];
        float4 k1 = *(const float4*)&Xt[e][s0 + 4];
        float qa[8] = {q0.x, q0.y, q0.z, q0.w, q1.x, q1.y, q1.z, q1.w};
        float ka[8] = {k0.x, k0.y, k0.z, k0.w, k1.x, k1.y, k1.z, k1.w};
        #pragma unroll
        for (int i = 0; i < 8; i++)
            #pragma unroll
            for (int j = 0; j < 8; j++)
                acc[i][j] += qa[i] * ka[j];
    }
    __syncthreads();   // all Kt reads done before overwrite

    // Causal mask (s <= t) and transposed store into At[s][t] (reusing Xt)
    #pragma unroll
    for (int j = 0; j < 8; j++) {
        int s = s0 + j;
        float m[8];
        #pragma unroll
        for (int i = 0; i < 8; i++) m[i] = (s <= t0 + i) ? acc[i][j] : 0.f;
        *(float4*)&Xt[s][t0]     = make_float4(m[0], m[1], m[2], m[3]);
        *(float4*)&Xt[s][t0 + 4] = make_float4(m[4], m[5], m[6], m[7]);
    }
    __syncthreads();

    // out accumulates Y tile [t0..t0+7][d0..d0+7]; reuse acc registers
    #pragma unroll
    for (int i = 0; i < 8; i++)
        #pragma unroll
        for (int j = 0; j < 8; j++) acc[i][j] = 0.f;

    // Phase B1: out += A[t][s] * V[s][d]
    #pragma unroll 4
    for (int s = 0; s < C_; s++) {
        float4 a0 = *(const float4*)&Xt[s][t0];
        float4 a1 = *(const float4*)&Xt[s][t0 + 4];
        float4 v0 = *(const float4*)&Vs[s][d0];
        float4 v1 = *(const float4*)&Vs[s][d0 + 4];
        float aa[8] = {a0.x, a0.y, a0.z, a0.w, a1.x, a1.y, a1.z, a1.w};
        float vw[8] = {v0.x, v0.y, v0.z, v0.w, v1.x, v1.y, v1.z, v1.w};
        #pragma unroll
        for (int i = 0; i < 8; i++)
            #pragma unroll
            for (int j = 0; j < 8; j++)
                acc[i][j] += aa[i] * vw[j];
    }
    __syncthreads();   // At consumed; reuse Xt for Mt

    // Load M (L2-resident scratch) transposed: Mt[e][d] = M[d][e]
    #pragma unroll
    for (int f = tid2; f < D_ * D_ / 4; f += 64) {
        int r = f >> 4;        // d row
        int cc = (f & 15) * 4; // e base
        float4 mv = *(const float4*)(Mbase + f * 4);
        Xt[cc + 0][r] = mv.x; Xt[cc + 1][r] = mv.y; Xt[cc + 2][r] = mv.z; Xt[cc + 3][r] = mv.w;
    }
    __syncthreads();

    // Phase B2: out += Q[t][e] * M[d][e]
    #pragma unroll 4
    for (int e = 0; e < D_; e++) {
        float4 q0 = *(const float4*)&Qt[e][t0];
        float4 q1 = *(const float4*)&Qt[e][t0 + 4];
        float4 m0 = *(const float4*)&Xt[e][d0];
        float4 m1 = *(const float4*)&Xt[e][d0 + 4];
        float qa[8] = {q0.x, q0.y, q0.z, q0.w, q1.x, q1.y, q1.z, q1.w};
        float ma[8] = {m0.x, m0.y, m0.z, m0.w, m1.x, m1.y, m1.z, m1.w};
        #pragma unroll
        for (int i = 0; i < 8; i++)
            #pragma unroll
            for (int j = 0; j < 8; j++)
                acc[i][j] += qa[i] * ma[j];
    }

    float* ybase = y + (((size_t)b * T_ + (size_t)c * C_) * H_ + h) * D_;
    #pragma unroll
    for (int i = 0; i < 8; i++) {
        *(float4*)(ybase + (size_t)(t0 + i) * ROWSTRIDE + d0) =
            make_float4(acc[i][0], acc[i][1], acc[i][2], acc[i][3]);
        *(float4*)(ybase + (size_t)(t0 + i) * ROWSTRIDE + d0 + 4) =
            make_float4(acc[i][4], acc[i][5], acc[i][6], acc[i][7]);
    }
}

// ---------------------------------------------------------------------------
extern "C" void kernel_launch(void* const* d_in, const int* in_sizes, int n_in,
                              void* d_out, int out_size) {
    (void)in_sizes; (void)n_in; (void)out_size;
    const float* q = (const float*)d_in[0];
    const float* k = (const float*)d_in[1];
    const float* v = (const float*)d_in[2];
    float* y = (float*)d_out;

    cudaFuncSetAttribute(chunk_sum_kernel, cudaFuncAttributeMaxDynamicSharedMemorySize,
                         SMEM1_BYTES);
    cudaFuncSetAttribute(output_kernel, cudaFuncAttributeMaxDynamicSharedMemorySize,
                         SMEM3_BYTES);

    chunk_sum_kernel<<<BH_ * NC_ / 2, 128, SMEM1_BYTES>>>(k, v);
    prefix_kernel<<<(BH_ * D_ * D_) / 256, 256>>>();
    output_kernel<<<BH_ * NC_ / 2, 128, SMEM3_BYTES>>>(q, k, v, y);
}